// round 9
// baseline (speedup 1.0000x reference)
#include <cuda_runtime.h>
#include <cuda_fp16.h>
#include <cstdint>

using u32 = uint32_t;

// ---------------- problem dims ----------------
constexpr int Mdim = 8192, Ndim = 4096, KL = 512, RANKS = 8;
constexpr int K4 = RANKS * KL;                 // 4096: plain fp16, 1:1 K packing

// ---------------- GEMM tiling ----------------
constexpr int BM = 128;                        // M per CTA
constexpr int BN = 128;                        // N per CTA
constexpr int BKB = 64;                        // fp16 k per SMEM stage (128B rows)
constexpr int NT = K4 / BKB;                   // 64 k-tiles
constexpr int THREADS = 256;                   // 8 warps: 2(m) x 4(n), warp 64x32

constexpr int A_BYTES = BM * 128;              // 16 KB
constexpr int B_BYTES = BN * 128;              // 16 KB
constexpr int STAGE_BYTES = A_BYTES + B_BYTES; // 32 KB
constexpr int STAGES = 3;
constexpr int SMEM_TOTAL = STAGES * STAGE_BYTES;   // 98304 -> 2 CTAs/SM

// ---------------- scratch (device globals = sanctioned scratch) ----------------
__device__ __half g_A2[(size_t)Mdim * K4];   // 67 MB : fl16(a)
__device__ __half g_B2[(size_t)Ndim * K4];   // 33 MB : fl16(b)

// ---------------- PTX helpers (arch-portable, sm_80+) ----------------
__device__ __forceinline__ u32 smem_u32(const void* p) {
    u32 r;
    asm("{ .reg .u64 t; cvta.to.shared.u64 t, %1; cvt.u32.u64 %0, t; }"
        : "=r"(r) : "l"(p));
    return r;
}
__device__ __forceinline__ u32 swz128(u32 off) { return off ^ ((off >> 3) & 0x70); }

__device__ __forceinline__ void cp_async16(u32 saddr, const void* gaddr) {
    asm volatile("cp.async.cg.shared.global [%0], [%1], 16;"
                 :: "r"(saddr), "l"(gaddr) : "memory");
}
__device__ __forceinline__ void cp_commit() {
    asm volatile("cp.async.commit_group;" ::: "memory");
}
__device__ __forceinline__ void cp_wait1() {
    asm volatile("cp.async.wait_group 1;" ::: "memory");
}

__device__ __forceinline__ void ldsm_x4(u32& r0, u32& r1, u32& r2, u32& r3, u32 a) {
    asm volatile("ldmatrix.sync.aligned.m8n8.x4.shared.b16 {%0,%1,%2,%3}, [%4];"
                 : "=r"(r0), "=r"(r1), "=r"(r2), "=r"(r3) : "r"(a));
}
__device__ __forceinline__ void hmma_f16(float* c, const u32* a, u32 b0, u32 b1) {
    asm volatile(
        "mma.sync.aligned.m16n8k16.row.col.f32.f16.f16.f32 "
        "{%0,%1,%2,%3}, {%4,%5,%6,%7}, {%8,%9}, {%0,%1,%2,%3};"
        : "+f"(c[0]), "+f"(c[1]), "+f"(c[2]), "+f"(c[3])
        : "r"(a[0]), "r"(a[1]), "r"(a[2]), "r"(a[3]), "r"(b0), "r"(b1));
}

// ---------------- conversion: fp32 -> fp16 (1:1) ----------------
__global__ void __launch_bounds__(256)
convert_kernel(const float* __restrict__ a, const float* __restrict__ b)
{
    constexpr size_t ACH = (size_t)RANKS * Mdim * KL / 8;   // 4,194,304
    constexpr size_t BCH = (size_t)RANKS * Ndim * KL / 8;   // 2,097,152
    size_t id = (size_t)blockIdx.x * 256 + threadIdx.x;
    if (id >= ACH + BCH) return;

    bool isA = id < ACH;
    size_t cid = isA ? id : id - ACH;

    size_t src_row = cid >> 6;            // 64 chunks of 8 floats per (src,row)
    int k0 = (int)(cid & 63) * 8;
    int srk, row;
    if (isA) { srk = (int)(src_row / Mdim); row = (int)(src_row % Mdim); }
    else     { srk = (int)(src_row / Ndim); row = (int)(src_row % Ndim); }

    const float* src = (isA ? a : b) + cid * 8;
    __half* dst = (isA ? g_A2 : g_B2)
        + (size_t)row * K4 + (size_t)(srk * KL + k0);

    float4 f0 = ((const float4*)src)[0];
    float4 f1 = ((const float4*)src)[1];
    float xs[8] = {f0.x, f0.y, f0.z, f0.w, f1.x, f1.y, f1.z, f1.w};

    __align__(16) __half ov[8];
#pragma unroll
    for (int i = 0; i < 8; i++) ov[i] = __float2half_rn(xs[i]);
    *(uint4*)dst = *(const uint4*)ov;
}

// ---------------- HMMA GEMM: C[8192,4096] = A2 @ B2^T ----------------
__global__ void __launch_bounds__(THREADS, 2)
gemm_mma_kernel(float* __restrict__ C)
{
    extern __shared__ __align__(1024) char smem[];
    const u32 sbase = smem_u32(smem);
    const int tid = threadIdx.x;
    const int lane = tid & 31;
    const int w = tid >> 5;            // 8 warps
    const int wm = w >> 2;             // 0..1 : warp row (64 M each)
    const int wn = w & 3;              // 0..3 : warp col (32 N each)

    const int m0 = blockIdx.y * BM;
    const int n0 = blockIdx.x * BN;

    // ---- cp.async mapping: 8 chunks/thread/stage (4 A + 4 B) ----
    const int lrow = tid >> 3;                    // 0..31
    const int lcol = tid & 7;                     // 0..7
    const u32 sA0 = swz128((u32)lrow * 128 + (u32)lcol * 16);
    const u32 sB0 = A_BYTES + sA0;                // same swizzle key (row&7 equal)
    // strength-reduced global pointers: advance by BKB each tile
    const __half* gA = g_A2 + (size_t)(m0 + lrow) * K4 + lcol * 8;
    const __half* gB = g_B2 + (size_t)(n0 + lrow) * K4 + lcol * 8;
    const __half* gAp = gA + 2 * BKB;             // prefetch cursor (tile t+2)
    const __half* gBp = gB + 2 * BKB;
    constexpr size_t RSTRIDE = (size_t)32 * K4;   // 32-row pointer stride

    // ---- ldmatrix address precomputation ----
    const u32 frag_xor = (u32)(lane & 7) * 16;
    const u32 khalf = (u32)((lane >> 4) & 1) * 16;
    const int frag_row = (((lane >> 3) & 1) << 3) + (lane & 7);
    u32 aPre[4];
#pragma unroll
    for (int mb = 0; mb < 4; mb++)
        aPre[mb] = (u32)(wm * 64 + mb * 16 + frag_row) * 128;
    u32 bPre[2];
#pragma unroll
    for (int nb = 0; nb < 2; nb++)
        bPre[nb] = (u32)(wn * 32 + nb * 16 + frag_row) * 128;

    float acc[4][4][4];
#pragma unroll
    for (int i = 0; i < 4; i++)
#pragma unroll
        for (int j = 0; j < 4; j++)
#pragma unroll
            for (int q = 0; q < 4; q++) acc[i][j][q] = 0.f;

    // ---- prologue: stage tiles 0..1 ----
#pragma unroll
    for (int p = 0; p < 2; p++) {
        const u32 sb = sbase + p * STAGE_BYTES;
#pragma unroll
        for (int i = 0; i < 4; i++)
            cp_async16(sb + sA0 + i * 4096, gA + (size_t)i * RSTRIDE + (size_t)p * BKB);
#pragma unroll
        for (int j = 0; j < 4; j++)
            cp_async16(sb + sB0 + j * 4096, gB + (size_t)j * RSTRIDE + (size_t)p * BKB);
        cp_commit();
    }

    // fragment double buffers
    u32 af[2][4][4];
    u32 bf[2][2][4];

    // ---- main loop ----
    // Order within a tile: barrier -> ldsm ks0 (critical path) -> prefetch
    // cp.asyncs -> ks loop with next-ks ldsm interleaved among HMMAs.
    // WAR safe: prefetch writes stage (t+2)%3 == (t-1)%3, whose readers
    // (compute t-1) all precede this iteration's __syncthreads.
    int stage = 0;
    for (int t = 0; t < NT; t++) {
        cp_wait1();                // tile t's group complete (own thread)
        __syncthreads();           // all threads' chunks of tile t visible

        const u32 sA = sbase + stage * STAGE_BYTES;
        const u32 sB = sA + A_BYTES;

        // ks=0 fragments FIRST (feed the first HMMAs asap)
        {
            const u32 kk = khalf ^ frag_xor;
#pragma unroll
            for (int mb = 0; mb < 4; mb++)
                ldsm_x4(af[0][mb][0], af[0][mb][1], af[0][mb][2], af[0][mb][3],
                        sA + aPre[mb] + kk);
#pragma unroll
            for (int nb = 0; nb < 2; nb++)
                ldsm_x4(bf[0][nb][0], bf[0][nb][1], bf[0][nb][2], bf[0][nb][3],
                        sB + bPre[nb] + kk);
        }

        // prefetch tile t+2 (behind the critical-path ldsm in the LSU queue)
        if (t + 2 < NT) {
            int ps = stage + 2; if (ps >= 3) ps -= 3;
            const u32 sb = sbase + ps * STAGE_BYTES;
#pragma unroll
            for (int i = 0; i < 4; i++)
                cp_async16(sb + sA0 + i * 4096, gAp + (size_t)i * RSTRIDE);
#pragma unroll
            for (int j = 0; j < 4; j++)
                cp_async16(sb + sB0 + j * 4096, gBp + (size_t)j * RSTRIDE);
        }
        cp_commit();               // one group per iter (empty near tail)
        gAp += BKB; gBp += BKB;

#pragma unroll
        for (int ks = 0; ks < 4; ks++) {
            const int cur = ks & 1;
            const int nxt = cur ^ 1;
            const u32 kk = ((u32)(ks + 1) * 32 + khalf) ^ frag_xor;
            const bool pf = (ks < 3);

            // interleave next-ks ldsm (6) among this ks's HMMAs (16):
            if (pf) {
                ldsm_x4(af[nxt][0][0], af[nxt][0][1], af[nxt][0][2], af[nxt][0][3],
                        sA + aPre[0] + kk);
                ldsm_x4(af[nxt][1][0], af[nxt][1][1], af[nxt][1][2], af[nxt][1][3],
                        sA + aPre[1] + kk);
            }
            hmma_f16(acc[0][0], af[cur][0], bf[cur][0][0], bf[cur][0][2]);
            hmma_f16(acc[0][1], af[cur][0], bf[cur][0][1], bf[cur][0][3]);
            hmma_f16(acc[0][2], af[cur][0], bf[cur][1][0], bf[cur][1][2]);
            if (pf)
                ldsm_x4(af[nxt][2][0], af[nxt][2][1], af[nxt][2][2], af[nxt][2][3],
                        sA + aPre[2] + kk);
            hmma_f16(acc[0][3], af[cur][0], bf[cur][1][1], bf[cur][1][3]);
            hmma_f16(acc[1][0], af[cur][1], bf[cur][0][0], bf[cur][0][2]);
            hmma_f16(acc[1][1], af[cur][1], bf[cur][0][1], bf[cur][0][3]);
            if (pf)
                ldsm_x4(af[nxt][3][0], af[nxt][3][1], af[nxt][3][2], af[nxt][3][3],
                        sA + aPre[3] + kk);
            hmma_f16(acc[1][2], af[cur][1], bf[cur][1][0], bf[cur][1][2]);
            hmma_f16(acc[1][3], af[cur][1], bf[cur][1][1], bf[cur][1][3]);
            if (pf)
                ldsm_x4(bf[nxt][0][0], bf[nxt][0][1], bf[nxt][0][2], bf[nxt][0][3],
                        sB + bPre[0] + kk);
            hmma_f16(acc[2][0], af[cur][2], bf[cur][0][0], bf[cur][0][2]);
            hmma_f16(acc[2][1], af[cur][2], bf[cur][0][1], bf[cur][0][3]);
            if (pf)
                ldsm_x4(bf[nxt][1][0], bf[nxt][1][1], bf[nxt][1][2], bf[nxt][1][3],
                        sB + bPre[1] + kk);
            hmma_f16(acc[2][2], af[cur][2], bf[cur][1][0], bf[cur][1][2]);
            hmma_f16(acc[2][3], af[cur][2], bf[cur][1][1], bf[cur][1][3]);
            hmma_f16(acc[3][0], af[cur][3], bf[cur][0][0], bf[cur][0][2]);
            hmma_f16(acc[3][1], af[cur][3], bf[cur][0][1], bf[cur][0][3]);
            hmma_f16(acc[3][2], af[cur][3], bf[cur][1][0], bf[cur][1][2]);
            hmma_f16(acc[3][3], af[cur][3], bf[cur][1][1], bf[cur][1][3]);
        }

        if (++stage == 3) stage = 0;
    }

    // ---- epilogue ----
    const int er = lane >> 2;
    const int ec = (lane & 3) * 2;
#pragma unroll
    for (int mb = 0; mb < 4; mb++) {
#pragma unroll
        for (int nb = 0; nb < 4; nb++) {
            float* base = C + (size_t)(m0 + wm * 64 + mb * 16 + er) * Ndim
                            + (n0 + wn * 32 + nb * 8 + ec);
            *(float2*)base = make_float2(acc[mb][nb][0], acc[mb][nb][1]);
            *(float2*)(base + (size_t)8 * Ndim) = make_float2(acc[mb][nb][2], acc[mb][nb][3]);
        }
    }
}

// ---------------- launch ----------------
extern "C" void kernel_launch(void* const* d_in, const int* in_sizes, int n_in,
                              void* d_out, int out_size)
{
    const float* a = (const float*)d_in[0];   // [8, 8192, 512] fp32
    const float* b = (const float*)d_in[1];   // [8, 4096, 512] fp32
    float* c = (float*)d_out;                 // [8192, 4096] fp32

    constexpr size_t TOTAL_CHUNKS =
        ((size_t)RANKS * Mdim * KL + (size_t)RANKS * Ndim * KL) / 8;  // 6,291,456
    convert_kernel<<<(unsigned)(TOTAL_CHUNKS / 256), 256>>>(a, b);

    cudaFuncSetAttribute(gemm_mma_kernel,
                         cudaFuncAttributeMaxDynamicSharedMemorySize, SMEM_TOTAL);
    dim3 grid(Ndim / BN, Mdim / BM);          // (32, 64) = 2048 CTAs, 2 per SM
    gemm_mma_kernel<<<grid, THREADS, SMEM_TOTAL>>>(c);
}

// round 10
// speedup vs baseline: 1.0856x; 1.0856x over previous
#include <cuda_runtime.h>
#include <cuda_fp16.h>
#include <cuda.h>
#include <cstdint>

using u32 = uint32_t;

// ---------------- problem dims ----------------
constexpr int Mdim = 8192, Ndim = 4096, KL = 512, RANKS = 8;
constexpr int K4 = RANKS * KL;                 // 4096: plain fp16, 1:1 K packing

// ---------------- GEMM tiling ----------------
constexpr int BM = 128;                        // M per CTA
constexpr int BN = 128;                        // N per CTA
constexpr int BKB = 64;                        // fp16 k per SMEM stage (128B rows)
constexpr int NT = K4 / BKB;                   // 64 k-tiles
constexpr int THREADS = 256;                   // 8 warps: 2(m) x 4(n), warp 64x32

constexpr int A_BYTES = BM * 128;              // 16 KB
constexpr int B_BYTES = BN * 128;              // 16 KB
constexpr int STAGE_BYTES = A_BYTES + B_BYTES; // 32 KB
constexpr int STAGES = 3;
constexpr int CTRL = STAGES * STAGE_BYTES;     // 98304
constexpr int SMEM_TOTAL = CTRL + 64;          // + 6 mbarriers -> 2 CTAs/SM

// ---------------- scratch (device globals = sanctioned scratch) ----------------
__device__ __half g_A2[(size_t)Mdim * K4];   // 67 MB : fl16(a)
__device__ __half g_B2[(size_t)Ndim * K4];   // 33 MB : fl16(b)

// ---------------- PTX helpers ----------------
__device__ __forceinline__ u32 smem_u32(const void* p) {
    u32 r;
    asm("{ .reg .u64 t; cvta.to.shared.u64 t, %1; cvt.u32.u64 %0, t; }"
        : "=r"(r) : "l"(p));
    return r;
}

__device__ __forceinline__ void mbar_init(u32 addr, u32 cnt) {
    asm volatile("mbarrier.init.shared.b64 [%0], %1;" :: "r"(addr), "r"(cnt) : "memory");
}
__device__ __forceinline__ void mbar_expect_tx(u32 addr, u32 bytes) {
    asm volatile("mbarrier.arrive.expect_tx.shared.b64 _, [%0], %1;"
                 :: "r"(addr), "r"(bytes) : "memory");
}
__device__ __forceinline__ void mbar_arrive(u32 addr) {
    asm volatile("mbarrier.arrive.shared.b64 _, [%0];" :: "r"(addr) : "memory");
}
__device__ __forceinline__ void mbar_wait(u32 addr, u32 parity) {
    asm volatile(
        "{\n\t.reg .pred P;\n"
        "WL%=:\n\t"
        "mbarrier.try_wait.parity.acquire.cta.shared::cta.b64 P, [%0], %1, 0x989680;\n\t"
        "@P bra WD%=;\n\t"
        "bra WL%=;\n"
        "WD%=:\n\t}"
        :: "r"(addr), "r"(parity) : "memory");
}

__device__ __forceinline__ void tma2d(u32 smem, const void* tmap, int x, int y, u32 mbar) {
    asm volatile(
        "cp.async.bulk.tensor.2d.shared::cta.global.tile.mbarrier::complete_tx::bytes "
        "[%0], [%1, {%2, %3}], [%4];"
        :: "r"(smem), "l"(tmap), "r"(x), "r"(y), "r"(mbar) : "memory");
}

__device__ __forceinline__ void ldsm_x4(u32& r0, u32& r1, u32& r2, u32& r3, u32 a) {
    asm volatile("ldmatrix.sync.aligned.m8n8.x4.shared.b16 {%0,%1,%2,%3}, [%4];"
                 : "=r"(r0), "=r"(r1), "=r"(r2), "=r"(r3) : "r"(a));
}
__device__ __forceinline__ void hmma_f16(float* c, const u32* a, u32 b0, u32 b1) {
    asm volatile(
        "mma.sync.aligned.m16n8k16.row.col.f32.f16.f16.f32 "
        "{%0,%1,%2,%3}, {%4,%5,%6,%7}, {%8,%9}, {%0,%1,%2,%3};"
        : "+f"(c[0]), "+f"(c[1]), "+f"(c[2]), "+f"(c[3])
        : "r"(a[0]), "r"(a[1]), "r"(a[2]), "r"(a[3]), "r"(b0), "r"(b1));
}

// ---------------- conversion: fp32 -> fp16 (1:1) ----------------
__global__ void __launch_bounds__(256)
convert_kernel(const float* __restrict__ a, const float* __restrict__ b)
{
    constexpr size_t ACH = (size_t)RANKS * Mdim * KL / 8;   // 4,194,304
    constexpr size_t BCH = (size_t)RANKS * Ndim * KL / 8;   // 2,097,152
    size_t id = (size_t)blockIdx.x * 256 + threadIdx.x;
    if (id >= ACH + BCH) return;

    bool isA = id < ACH;
    size_t cid = isA ? id : id - ACH;

    size_t src_row = cid >> 6;            // 64 chunks of 8 floats per (src,row)
    int k0 = (int)(cid & 63) * 8;
    int srk, row;
    if (isA) { srk = (int)(src_row / Mdim); row = (int)(src_row % Mdim); }
    else     { srk = (int)(src_row / Ndim); row = (int)(src_row % Ndim); }

    const float* src = (isA ? a : b) + cid * 8;
    __half* dst = (isA ? g_A2 : g_B2)
        + (size_t)row * K4 + (size_t)(srk * KL + k0);

    float4 f0 = ((const float4*)src)[0];
    float4 f1 = ((const float4*)src)[1];
    float xs[8] = {f0.x, f0.y, f0.z, f0.w, f1.x, f1.y, f1.z, f1.w};

    __align__(16) __half ov[8];
#pragma unroll
    for (int i = 0; i < 8; i++) ov[i] = __float2half_rn(xs[i]);
    *(uint4*)dst = *(const uint4*)ov;
}

// ---------------- HMMA GEMM with TMA + mbarrier pipeline ----------------
__global__ void __launch_bounds__(THREADS, 2)
gemm_mma_kernel(const __grid_constant__ CUtensorMap tmA,
                const __grid_constant__ CUtensorMap tmB,
                float* __restrict__ C)
{
    extern __shared__ __align__(1024) char smem[];
    const u32 sbase = smem_u32(smem);
    const int tid = threadIdx.x;
    const int lane = tid & 31;
    const int w = tid >> 5;            // 8 warps
    const int wm = w >> 2;             // 0..1 : warp row (64 M each)
    const int wn = w & 3;              // 0..3 : warp col (32 N each)

    const int m0 = blockIdx.y * BM;
    const int n0 = blockIdx.x * BN;

    const u32 mb_full = sbase + CTRL;          // 3 x u64
    const u32 mb_empty = sbase + CTRL + 24;    // 3 x u64

    if (tid == 0) {
#pragma unroll
        for (int s = 0; s < 3; s++) {
            mbar_init(mb_full + s * 8, 1);
            mbar_init(mb_empty + s * 8, THREADS);
        }
    }
    __syncthreads();
    asm volatile("fence.proxy.async.shared::cta;" ::: "memory");

    // ---- prologue: TMA tiles 0,1 into stages 0,1 ----
    if (tid == 0) {
#pragma unroll
        for (int p = 0; p < 2; p++) {
            mbar_expect_tx(mb_full + p * 8, STAGE_BYTES);
            tma2d(sbase + p * STAGE_BYTES,           &tmA, p * BKB, m0, mb_full + p * 8);
            tma2d(sbase + p * STAGE_BYTES + A_BYTES, &tmB, p * BKB, n0, mb_full + p * 8);
        }
    }

    // ---- ldmatrix address precomputation ----
    const u32 frag_xor = (u32)(lane & 7) * 16;
    const u32 khalf = (u32)((lane >> 4) & 1) * 16;
    const int frag_row = (((lane >> 3) & 1) << 3) + (lane & 7);
    u32 aPre[4];
#pragma unroll
    for (int mb = 0; mb < 4; mb++)
        aPre[mb] = (u32)(wm * 64 + mb * 16 + frag_row) * 128;
    u32 bPre[2];
#pragma unroll
    for (int nb = 0; nb < 2; nb++)
        bPre[nb] = (u32)(wn * 32 + nb * 16 + frag_row) * 128;

    float acc[4][4][4];
#pragma unroll
    for (int i = 0; i < 4; i++)
#pragma unroll
        for (int j = 0; j < 4; j++)
#pragma unroll
            for (int q = 0; q < 4; q++) acc[i][j][q] = 0.f;

    u32 af[2][4][4];
    u32 bf[2][2][4];

    // ---- main loop ----
    // Producer (tid 0): at iter t, issue tile t+2 into stage (t+2)%3 after
    // waiting empty (all 256 consumers arrived for that stage's previous use).
    // Consumers: wait full[t%3] parity, compute, arrive empty[t%3].
    int stage = 0, fpar = 0, epar = 0;
    for (int t = 0; t < NT; t++) {
        int s2 = stage + 2; if (s2 >= 3) s2 -= 3;
        if (t + 2 < NT) {
            if (tid == 0) {
                if (t + 2 >= 3) mbar_wait(mb_empty + s2 * 8, (u32)epar);
                mbar_expect_tx(mb_full + s2 * 8, STAGE_BYTES);
                tma2d(sbase + s2 * STAGE_BYTES,           &tmA, (t + 2) * BKB, m0,
                      mb_full + s2 * 8);
                tma2d(sbase + s2 * STAGE_BYTES + A_BYTES, &tmB, (t + 2) * BKB, n0,
                      mb_full + s2 * 8);
            }
            if (t + 2 >= 3 && s2 == 2) epar ^= 1;
        }

        mbar_wait(mb_full + stage * 8, (u32)fpar);

        const u32 sA = sbase + stage * STAGE_BYTES;
        const u32 sB = sA + A_BYTES;

        // ks=0 fragments
        {
            const u32 kk = khalf ^ frag_xor;
#pragma unroll
            for (int mb = 0; mb < 4; mb++)
                ldsm_x4(af[0][mb][0], af[0][mb][1], af[0][mb][2], af[0][mb][3],
                        sA + aPre[mb] + kk);
#pragma unroll
            for (int nb = 0; nb < 2; nb++)
                ldsm_x4(bf[0][nb][0], bf[0][nb][1], bf[0][nb][2], bf[0][nb][3],
                        sB + bPre[nb] + kk);
        }

#pragma unroll
        for (int ks = 0; ks < 4; ks++) {
            const int cur = ks & 1;
            if (ks < 3) {           // prefetch next ks fragments before HMMAs
                const int nxt = cur ^ 1;
                const u32 kk = ((u32)(ks + 1) * 32 + khalf) ^ frag_xor;
#pragma unroll
                for (int mb = 0; mb < 4; mb++)
                    ldsm_x4(af[nxt][mb][0], af[nxt][mb][1], af[nxt][mb][2], af[nxt][mb][3],
                            sA + aPre[mb] + kk);
#pragma unroll
                for (int nb = 0; nb < 2; nb++)
                    ldsm_x4(bf[nxt][nb][0], bf[nxt][nb][1], bf[nxt][nb][2], bf[nxt][nb][3],
                            sB + bPre[nb] + kk);
            }
#pragma unroll
            for (int mb = 0; mb < 4; mb++)
#pragma unroll
                for (int nb = 0; nb < 2; nb++) {
                    hmma_f16(acc[mb][2 * nb + 0], af[cur][mb], bf[cur][nb][0], bf[cur][nb][2]);
                    hmma_f16(acc[mb][2 * nb + 1], af[cur][mb], bf[cur][nb][1], bf[cur][nb][3]);
                }
        }

        mbar_arrive(mb_empty + stage * 8);
        if (++stage == 3) { stage = 0; fpar ^= 1; }
    }

    // ---- epilogue ----
    const int er = lane >> 2;
    const int ec = (lane & 3) * 2;
#pragma unroll
    for (int mb = 0; mb < 4; mb++) {
#pragma unroll
        for (int nb = 0; nb < 4; nb++) {
            float* base = C + (size_t)(m0 + wm * 64 + mb * 16 + er) * Ndim
                            + (n0 + wn * 32 + nb * 8 + ec);
            *(float2*)base = make_float2(acc[mb][nb][0], acc[mb][nb][1]);
            *(float2*)(base + (size_t)8 * Ndim) = make_float2(acc[mb][nb][2], acc[mb][nb][3]);
        }
    }
}

// ---------------- launch ----------------
typedef CUresult (*tmap_encode_fn)(
    CUtensorMap*, CUtensorMapDataType, cuuint32_t, void*,
    const cuuint64_t*, const cuuint64_t*, const cuuint32_t*, const cuuint32_t*,
    CUtensorMapInterleave, CUtensorMapSwizzle, CUtensorMapL2promotion,
    CUtensorMapFloatOOBfill);

extern "C" void kernel_launch(void* const* d_in, const int* in_sizes, int n_in,
                              void* d_out, int out_size)
{
    const float* a = (const float*)d_in[0];   // [8, 8192, 512] fp32
    const float* b = (const float*)d_in[1];   // [8, 4096, 512] fp32
    float* c = (float*)d_out;                 // [8192, 4096] fp32

    constexpr size_t TOTAL_CHUNKS =
        ((size_t)RANKS * Mdim * KL + (size_t)RANKS * Ndim * KL) / 8;  // 6,291,456
    convert_kernel<<<(unsigned)(TOTAL_CHUNKS / 256), 256>>>(a, b);

    // Build tensormaps (host-side, deterministic, no allocation)
    void* pa = nullptr; void* pb = nullptr;
    cudaGetSymbolAddress(&pa, g_A2);
    cudaGetSymbolAddress(&pb, g_B2);

    void* fn = nullptr;
    cudaDriverEntryPointQueryResult qr;
    cudaGetDriverEntryPointByVersion("cuTensorMapEncodeTiled", &fn, 12000,
                                     cudaEnableDefault, &qr);
    tmap_encode_fn enc = (tmap_encode_fn)fn;

    CUtensorMap tA, tB;
    cuuint64_t dimsA[2] = {(cuuint64_t)K4, (cuuint64_t)Mdim};
    cuuint64_t dimsB[2] = {(cuuint64_t)K4, (cuuint64_t)Ndim};
    cuuint64_t strides[1] = {(cuuint64_t)K4 * 2};
    cuuint32_t box[2] = {(cuuint32_t)BKB, (cuuint32_t)BM};   // 64 x 128 (=128B x 128 rows)
    cuuint32_t es[2] = {1, 1};
    enc(&tA, CU_TENSOR_MAP_DATA_TYPE_FLOAT16, 2, pa, dimsA, strides, box, es,
        CU_TENSOR_MAP_INTERLEAVE_NONE, CU_TENSOR_MAP_SWIZZLE_128B,
        CU_TENSOR_MAP_L2_PROMOTION_L2_128B, CU_TENSOR_MAP_FLOAT_OOB_FILL_NONE);
    enc(&tB, CU_TENSOR_MAP_DATA_TYPE_FLOAT16, 2, pb, dimsB, strides, box, es,
        CU_TENSOR_MAP_INTERLEAVE_NONE, CU_TENSOR_MAP_SWIZZLE_128B,
        CU_TENSOR_MAP_L2_PROMOTION_L2_128B, CU_TENSOR_MAP_FLOAT_OOB_FILL_NONE);

    cudaFuncSetAttribute(gemm_mma_kernel,
                         cudaFuncAttributeMaxDynamicSharedMemorySize, SMEM_TOTAL);
    dim3 grid(Ndim / BN, Mdim / BM);          // (32, 64) = 2048 CTAs, 2 per SM
    gemm_mma_kernel<<<grid, THREADS, SMEM_TOTAL>>>(tA, tB, c);
}

// round 11
// speedup vs baseline: 1.2377x; 1.1401x over previous
#include <cuda_runtime.h>
#include <cuda_fp16.h>
#include <cuda.h>
#include <cstdint>

using u32 = uint32_t;

// ---------------- problem dims ----------------
constexpr int Mdim = 8192, Ndim = 4096, KL = 512, RANKS = 8;
constexpr int K4 = RANKS * KL;                 // 4096: plain fp16, 1:1 K packing

// ---------------- GEMM tiling ----------------
constexpr int BM = 128;                        // M per CTA
constexpr int BN = 128;                        // N per CTA
constexpr int BKB = 64;                        // fp16 k per SMEM stage (128B rows)
constexpr int NT = K4 / BKB;                   // 64 k-tiles
constexpr int THREADS = 256;                   // 8 warps: 2(m) x 4(n), warp 64x32

constexpr int A_BYTES = BM * 128;              // 16 KB
constexpr int B_BYTES = BN * 128;              // 16 KB
constexpr int STAGE_BYTES = A_BYTES + B_BYTES; // 32 KB
constexpr int STAGES = 3;
constexpr int CTRL = STAGES * STAGE_BYTES;     // 98304
constexpr int SMEM_TOTAL = CTRL + 64;          // + 6 mbarriers -> 2 CTAs/SM

// ---------------- scratch (device globals = sanctioned scratch) ----------------
__device__ __half g_A2[(size_t)Mdim * K4];   // 67 MB : fl16(a)
__device__ __half g_B2[(size_t)Ndim * K4];   // 33 MB : fl16(b)

// ---------------- PTX helpers ----------------
__device__ __forceinline__ u32 smem_u32(const void* p) {
    u32 r;
    asm("{ .reg .u64 t; cvta.to.shared.u64 t, %1; cvt.u32.u64 %0, t; }"
        : "=r"(r) : "l"(p));
    return r;
}

__device__ __forceinline__ void mbar_init(u32 addr, u32 cnt) {
    asm volatile("mbarrier.init.shared.b64 [%0], %1;" :: "r"(addr), "r"(cnt) : "memory");
}
__device__ __forceinline__ void mbar_expect_tx(u32 addr, u32 bytes) {
    asm volatile("mbarrier.arrive.expect_tx.shared.b64 _, [%0], %1;"
                 :: "r"(addr), "r"(bytes) : "memory");
}
__device__ __forceinline__ void mbar_arrive(u32 addr) {
    asm volatile("mbarrier.arrive.shared.b64 _, [%0];" :: "r"(addr) : "memory");
}
__device__ __forceinline__ void mbar_wait(u32 addr, u32 parity) {
    asm volatile(
        "{\n\t.reg .pred P;\n"
        "WL%=:\n\t"
        "mbarrier.try_wait.parity.acquire.cta.shared::cta.b64 P, [%0], %1, 0x989680;\n\t"
        "@P bra WD%=;\n\t"
        "bra WL%=;\n"
        "WD%=:\n\t}"
        :: "r"(addr), "r"(parity) : "memory");
}

__device__ __forceinline__ void tma2d(u32 smem, const void* tmap, int x, int y, u32 mbar) {
    asm volatile(
        "cp.async.bulk.tensor.2d.shared::cta.global.tile.mbarrier::complete_tx::bytes "
        "[%0], [%1, {%2, %3}], [%4];"
        :: "r"(smem), "l"(tmap), "r"(x), "r"(y), "r"(mbar) : "memory");
}

__device__ __forceinline__ void ldsm_x4(u32& r0, u32& r1, u32& r2, u32& r3, u32 a) {
    asm volatile("ldmatrix.sync.aligned.m8n8.x4.shared.b16 {%0,%1,%2,%3}, [%4];"
                 : "=r"(r0), "=r"(r1), "=r"(r2), "=r"(r3) : "r"(a));
}
__device__ __forceinline__ void hmma_f16(float* c, const u32* a, u32 b0, u32 b1) {
    asm volatile(
        "mma.sync.aligned.m16n8k16.row.col.f32.f16.f16.f32 "
        "{%0,%1,%2,%3}, {%4,%5,%6,%7}, {%8,%9}, {%0,%1,%2,%3};"
        : "+f"(c[0]), "+f"(c[1]), "+f"(c[2]), "+f"(c[3])
        : "r"(a[0]), "r"(a[1]), "r"(a[2]), "r"(a[3]), "r"(b0), "r"(b1));
}

// ---------------- conversion: fp32 -> fp16 (1:1) ----------------
__global__ void __launch_bounds__(256)
convert_kernel(const float* __restrict__ a, const float* __restrict__ b)
{
    constexpr size_t ACH = (size_t)RANKS * Mdim * KL / 8;   // 4,194,304
    constexpr size_t BCH = (size_t)RANKS * Ndim * KL / 8;   // 2,097,152
    size_t id = (size_t)blockIdx.x * 256 + threadIdx.x;
    if (id >= ACH + BCH) return;

    bool isA = id < ACH;
    size_t cid = isA ? id : id - ACH;

    size_t src_row = cid >> 6;            // 64 chunks of 8 floats per (src,row)
    int k0 = (int)(cid & 63) * 8;
    int srk, row;
    if (isA) { srk = (int)(src_row / Mdim); row = (int)(src_row % Mdim); }
    else     { srk = (int)(src_row / Ndim); row = (int)(src_row % Ndim); }

    const float* src = (isA ? a : b) + cid * 8;
    __half* dst = (isA ? g_A2 : g_B2)
        + (size_t)row * K4 + (size_t)(srk * KL + k0);

    float4 f0 = ((const float4*)src)[0];
    float4 f1 = ((const float4*)src)[1];
    float xs[8] = {f0.x, f0.y, f0.z, f0.w, f1.x, f1.y, f1.z, f1.w};

    __align__(16) __half ov[8];
#pragma unroll
    for (int i = 0; i < 8; i++) ov[i] = __float2half_rn(xs[i]);
    *(uint4*)dst = *(const uint4*)ov;
}

// ---------------- HMMA GEMM with TMA + mbarrier pipeline ----------------
__global__ void __launch_bounds__(THREADS, 2)
gemm_mma_kernel(const __grid_constant__ CUtensorMap tmA,
                const __grid_constant__ CUtensorMap tmB,
                float* __restrict__ C)
{
    extern __shared__ __align__(1024) char smem[];
    const u32 sbase = smem_u32(smem);
    const int tid = threadIdx.x;
    const int lane = tid & 31;
    const int w = tid >> 5;            // 8 warps
    const int wm = w >> 2;             // 0..1 : warp row (64 M each)
    const int wn = w & 3;              // 0..3 : warp col (32 N each)

    const int m0 = blockIdx.y * BM;
    const int n0 = blockIdx.x * BN;

    const u32 mb_full = sbase + CTRL;          // 3 x u64
    const u32 mb_empty = sbase + CTRL + 24;    // 3 x u64

    if (tid == 0) {
#pragma unroll
        for (int s = 0; s < 3; s++) {
            mbar_init(mb_full + s * 8, 1);
            mbar_init(mb_empty + s * 8, 8);    // one arrive per warp
        }
    }
    __syncthreads();
    asm volatile("fence.proxy.async.shared::cta;" ::: "memory");

    // ---- prologue: TMA tiles 0,1 into stages 0,1 ----
    if (tid == 0) {
#pragma unroll
        for (int p = 0; p < 2; p++) {
            mbar_expect_tx(mb_full + p * 8, STAGE_BYTES);
            tma2d(sbase + p * STAGE_BYTES,           &tmA, p * BKB, m0, mb_full + p * 8);
            tma2d(sbase + p * STAGE_BYTES + A_BYTES, &tmB, p * BKB, n0, mb_full + p * 8);
        }
    }

    // ---- ldmatrix address precomputation ----
    const u32 frag_xor = (u32)(lane & 7) * 16;
    const u32 khalf = (u32)((lane >> 4) & 1) * 16;
    const int frag_row = (((lane >> 3) & 1) << 3) + (lane & 7);
    u32 aPre[4];
#pragma unroll
    for (int mb = 0; mb < 4; mb++)
        aPre[mb] = (u32)(wm * 64 + mb * 16 + frag_row) * 128;
    u32 bPre[2];
#pragma unroll
    for (int nb = 0; nb < 2; nb++)
        bPre[nb] = (u32)(wn * 32 + nb * 16 + frag_row) * 128;

    float acc[4][4][4];
#pragma unroll
    for (int i = 0; i < 4; i++)
#pragma unroll
        for (int j = 0; j < 4; j++)
#pragma unroll
            for (int q = 0; q < 4; q++) acc[i][j][q] = 0.f;

    u32 af[2][4][4];
    u32 bf[2][2][4];

    auto ldsm_all = [&](int buf, u32 sA_, u32 sB_, u32 kbyte) {
        const u32 kk = (kbyte + khalf) ^ frag_xor;
#pragma unroll
        for (int mb = 0; mb < 4; mb++)
            ldsm_x4(af[buf][mb][0], af[buf][mb][1], af[buf][mb][2], af[buf][mb][3],
                    sA_ + aPre[mb] + kk);
#pragma unroll
        for (int nb = 0; nb < 2; nb++)
            ldsm_x4(bf[buf][nb][0], bf[buf][nb][1], bf[buf][nb][2], bf[buf][nb][3],
                    sB_ + bPre[nb] + kk);
    };
    auto hmma_all = [&](int buf) {
#pragma unroll
        for (int mb = 0; mb < 4; mb++)
#pragma unroll
            for (int nb = 0; nb < 2; nb++) {
                hmma_f16(acc[mb][2 * nb + 0], af[buf][mb], bf[buf][nb][0], bf[buf][nb][2]);
                hmma_f16(acc[mb][2 * nb + 1], af[buf][mb], bf[buf][nb][1], bf[buf][nb][3]);
            }
    };

    // ---- steady-state entry: tile 0 ks0 fragments resident before the loop ----
    mbar_wait(mb_full + 0, 0);
    ldsm_all(0, sbase, sbase + A_BYTES, 0);

    // ---- main loop ----
    // Tile t body: [ks0 frags already in buf0]
    //   producer: TMA tile t+2
    //   ldsm ks1; HMMA ks0 | ldsm ks2; HMMA ks1 | ldsm ks3; HMMA ks2
    //   per-warp arrive empty(stage)            (stage reads done)
    //   HMMA ks3 (issued) ; wait full(t+1) ; ldsm(t+1, ks0)  -> next tile opens hot
    int stage = 0, fpar = 0, epar = 0;
    for (int t = 0; t < NT; t++) {
        int s2 = stage + 2; if (s2 >= 3) s2 -= 3;
        if (t + 2 < NT) {
            if (tid == 0) {
                if (t + 2 >= 3) mbar_wait(mb_empty + s2 * 8, (u32)epar);
                mbar_expect_tx(mb_full + s2 * 8, STAGE_BYTES);
                tma2d(sbase + s2 * STAGE_BYTES,           &tmA, (t + 2) * BKB, m0,
                      mb_full + s2 * 8);
                tma2d(sbase + s2 * STAGE_BYTES + A_BYTES, &tmB, (t + 2) * BKB, n0,
                      mb_full + s2 * 8);
            }
            if (t + 2 >= 3 && s2 == 2) epar ^= 1;
        }

        const u32 sA = sbase + stage * STAGE_BYTES;
        const u32 sB = sA + A_BYTES;

        ldsm_all(1, sA, sB, 32);   hmma_all(0);
        ldsm_all(0, sA, sB, 64);   hmma_all(1);
        ldsm_all(1, sA, sB, 96);   hmma_all(0);

        // all reads of this stage are issued; release it (one arrive per warp)
        __syncwarp();
        if (lane == 0) mbar_arrive(mb_empty + stage * 8);

        hmma_all(1);               // ks3 HMMAs queued into the tensor pipe

        if (t + 1 < NT) {          // overlap next-tile wait+ldsm with ks3 drain
            int ns = stage + 1; if (ns >= 3) ns -= 3;
            const u32 npar = (stage == 2) ? (u32)(fpar ^ 1) : (u32)fpar;
            mbar_wait(mb_full + ns * 8, npar);
            const u32 nA = sbase + ns * STAGE_BYTES;
            ldsm_all(0, nA, nA + A_BYTES, 0);
        }

        if (++stage == 3) { stage = 0; fpar ^= 1; }
    }

    // ---- epilogue ----
    const int er = lane >> 2;
    const int ec = (lane & 3) * 2;
#pragma unroll
    for (int mb = 0; mb < 4; mb++) {
#pragma unroll
        for (int nb = 0; nb < 4; nb++) {
            float* base = C + (size_t)(m0 + wm * 64 + mb * 16 + er) * Ndim
                            + (n0 + wn * 32 + nb * 8 + ec);
            *(float2*)base = make_float2(acc[mb][nb][0], acc[mb][nb][1]);
            *(float2*)(base + (size_t)8 * Ndim) = make_float2(acc[mb][nb][2], acc[mb][nb][3]);
        }
    }
}

// ---------------- launch ----------------
typedef CUresult (*tmap_encode_fn)(
    CUtensorMap*, CUtensorMapDataType, cuuint32_t, void*,
    const cuuint64_t*, const cuuint64_t*, const cuuint32_t*, const cuuint32_t*,
    CUtensorMapInterleave, CUtensorMapSwizzle, CUtensorMapL2promotion,
    CUtensorMapFloatOOBfill);

extern "C" void kernel_launch(void* const* d_in, const int* in_sizes, int n_in,
                              void* d_out, int out_size)
{
    const float* a = (const float*)d_in[0];   // [8, 8192, 512] fp32
    const float* b = (const float*)d_in[1];   // [8, 4096, 512] fp32
    float* c = (float*)d_out;                 // [8192, 4096] fp32

    constexpr size_t TOTAL_CHUNKS =
        ((size_t)RANKS * Mdim * KL + (size_t)RANKS * Ndim * KL) / 8;  // 6,291,456
    convert_kernel<<<(unsigned)(TOTAL_CHUNKS / 256), 256>>>(a, b);

    // Build tensormaps (host-side, deterministic, no allocation)
    void* pa = nullptr; void* pb = nullptr;
    cudaGetSymbolAddress(&pa, g_A2);
    cudaGetSymbolAddress(&pb, g_B2);

    void* fn = nullptr;
    cudaDriverEntryPointQueryResult qr;
    cudaGetDriverEntryPointByVersion("cuTensorMapEncodeTiled", &fn, 12000,
                                     cudaEnableDefault, &qr);
    tmap_encode_fn enc = (tmap_encode_fn)fn;

    CUtensorMap tA, tB;
    cuuint64_t dimsA[2] = {(cuuint64_t)K4, (cuuint64_t)Mdim};
    cuuint64_t dimsB[2] = {(cuuint64_t)K4, (cuuint64_t)Ndim};
    cuuint64_t strides[1] = {(cuuint64_t)K4 * 2};
    cuuint32_t box[2] = {(cuuint32_t)BKB, (cuuint32_t)BM};   // 64 x 128 (=128B x 128 rows)
    cuuint32_t es[2] = {1, 1};
    enc(&tA, CU_TENSOR_MAP_DATA_TYPE_FLOAT16, 2, pa, dimsA, strides, box, es,
        CU_TENSOR_MAP_INTERLEAVE_NONE, CU_TENSOR_MAP_SWIZZLE_128B,
        CU_TENSOR_MAP_L2_PROMOTION_L2_128B, CU_TENSOR_MAP_FLOAT_OOB_FILL_NONE);
    enc(&tB, CU_TENSOR_MAP_DATA_TYPE_FLOAT16, 2, pb, dimsB, strides, box, es,
        CU_TENSOR_MAP_INTERLEAVE_NONE, CU_TENSOR_MAP_SWIZZLE_128B,
        CU_TENSOR_MAP_L2_PROMOTION_L2_128B, CU_TENSOR_MAP_FLOAT_OOB_FILL_NONE);

    cudaFuncSetAttribute(gemm_mma_kernel,
                         cudaFuncAttributeMaxDynamicSharedMemorySize, SMEM_TOTAL);
    dim3 grid(Ndim / BN, Mdim / BM);          // (32, 64) = 2048 CTAs, 2 per SM
    gemm_mma_kernel<<<grid, THREADS, SMEM_TOTAL>>>(tA, tB, c);
}